// round 14
// baseline (speedup 1.0000x reference)
#include <cuda_runtime.h>
#include <cuda_bf16.h>
#include <cuda_fp16.h>
#include <math.h>
#include <stdint.h>

// ---------------- problem constants ----------------
#define HID   2048
#define NH    32
#define NKVH  8
#define HD    64
#define FF    8192
#define SEQ   2048
#define NB    2
#define ROWS  4096
#define EPS   1e-6f
#define MEG   (1024*1024)
#define L2E   1.4426950408889634f
#define NT    (SEQ / 64)

// ---------------- scratch (device globals; no allocs allowed) ----------------
__device__ float  g_res2[(size_t)ROWS * 2048];
__device__ __half g_qkvh[(size_t)ROWS * 3072];
__device__ __half g_m  [(size_t)ROWS * FF];

__device__ __half g_a  [(size_t)ROWS * HID];
__device__ __half g_w  [(size_t)58 * MEG];

__device__ __half g_q  [(size_t)ROWS * 2048];
__device__ __half g_k  [(size_t)ROWS * 512];
__device__ __half g_vt [(size_t)ROWS * 512];

// ---------------- helpers ----------------
__device__ __forceinline__ uint32_t smem_u32(const void* p) {
    uint32_t a;
    asm("{ .reg .u64 t; cvta.to.shared.u64 t, %1; cvt.u32.u64 %0, t; }" : "=r"(a) : "l"(p));
    return a;
}

__device__ __forceinline__ void cpa16(uint32_t dst, const void* src) {
    asm volatile("cp.async.cg.shared.global [%0], [%1], 16;" :: "r"(dst), "l"(src));
}
__device__ __forceinline__ void cpa_commit() {
    asm volatile("cp.async.commit_group;" ::: "memory");
}

__device__ __forceinline__ void ldsm4(uint32_t* r, uint32_t addr) {
    asm volatile("ldmatrix.sync.aligned.m8n8.x4.shared.b16 {%0,%1,%2,%3}, [%4];"
        : "=r"(r[0]), "=r"(r[1]), "=r"(r[2]), "=r"(r[3]) : "r"(addr));
}

__device__ __forceinline__ void mma_f16(float* c, const uint32_t* a, const uint32_t* b) {
    asm volatile("mma.sync.aligned.m16n8k16.row.col.f32.f16.f16.f32 "
        "{%0,%1,%2,%3}, {%4,%5,%6,%7}, {%8,%9}, {%0,%1,%2,%3};"
        : "+f"(c[0]), "+f"(c[1]), "+f"(c[2]), "+f"(c[3])
        : "r"(a[0]), "r"(a[1]), "r"(a[2]), "r"(a[3]), "r"(b[0]), "r"(b[1]));
}

__device__ __forceinline__ float fexp2(float z) {
    z = fminf(fmaxf(z, -126.f), 126.f);
    float sh = z + 12582912.f;
    float zi = sh - 12582912.f;
    float f = z - zi;
    float p = 0.0013333558f;
    p = p * f + 0.0096181291f;
    p = p * f + 0.0555041087f;
    p = p * f + 0.2402265070f;
    p = p * f + 0.6931471806f;
    p = p * f + 1.0f;
    int ei = __float_as_int(sh) - 0x4B400000;
    return p * __int_as_float((ei + 127) << 23);
}

__device__ __forceinline__ float fsilu(float x) {
    return x / (1.f + fexp2(-x * L2E));
}

// ---------------- converters ----------------
__global__ void convT_kernel(const float* __restrict__ W,
                             __half* __restrict__ wT, int K, int N)
{
    __shared__ float t[64][67];
    int n0 = blockIdx.x * 64, k0 = blockIdx.y * 64;
    int tx = threadIdx.x & 31, ty = threadIdx.x >> 5;
    int cx = threadIdx.x & 15;
    int ry = threadIdx.x >> 4;
    for (int ky = ry; ky < 64; ky += 16) {
        float4 v = *(const float4*)(W + (size_t)(k0 + ky) * N + n0 + cx * 4);
        t[ky][cx * 4 + 0] = v.x; t[ky][cx * 4 + 1] = v.y;
        t[ky][cx * 4 + 2] = v.z; t[ky][cx * 4 + 3] = v.w;
    }
    __syncthreads();
    for (int ny = ty; ny < 64; ny += 8) {
        __half2 h;
        h.x = __float2half_rn(t[2 * tx][ny]);
        h.y = __float2half_rn(t[2 * tx + 1][ny]);
        *(__half2*)(wT + (size_t)(n0 + ny) * K + k0 + 2 * tx) = h;
    }
}

__global__ void convT_gu_kernel(const float* __restrict__ G,
                                const float* __restrict__ U,
                                __half* __restrict__ wT, int K)
{
    __shared__ float tg[64][67];
    __shared__ float tu[64][67];
    int n0 = blockIdx.x * 64, k0 = blockIdx.y * 64;
    int tx = threadIdx.x & 31, ty = threadIdx.x >> 5;
    int cx = threadIdx.x & 15;
    int ry = threadIdx.x >> 4;
    for (int ky = ry; ky < 64; ky += 16) {
        float4 v = *(const float4*)(G + (size_t)(k0 + ky) * FF + n0 + cx * 4);
        tg[ky][cx * 4 + 0] = v.x; tg[ky][cx * 4 + 1] = v.y;
        tg[ky][cx * 4 + 2] = v.z; tg[ky][cx * 4 + 3] = v.w;
        float4 u = *(const float4*)(U + (size_t)(k0 + ky) * FF + n0 + cx * 4);
        tu[ky][cx * 4 + 0] = u.x; tu[ky][cx * 4 + 1] = u.y;
        tu[ky][cx * 4 + 2] = u.z; tu[ky][cx * 4 + 3] = u.w;
    }
    __syncthreads();
    for (int ny = ty; ny < 64; ny += 8) {
        int n = n0 + ny;
        size_t rowG = (size_t)((n >> 7) * 256 + ((n >> 6) & 1) * 128 + ((n >> 3) & 7) * 16 + (n & 7));
        __half2 h;
        h.x = __float2half_rn(tg[2 * tx][ny]);
        h.y = __float2half_rn(tg[2 * tx + 1][ny]);
        *(__half2*)(wT + rowG * K + k0 + 2 * tx) = h;
        h.x = __float2half_rn(tu[2 * tx][ny]);
        h.y = __float2half_rn(tu[2 * tx + 1][ny]);
        *(__half2*)(wT + (rowG + 8) * K + k0 + 2 * tx) = h;
    }
}

// RMSNorm -> fp16
__global__ void rmsnorm_h_kernel(const float* __restrict__ x,
                                 const float* __restrict__ w,
                                 __half* __restrict__ o, int K)
{
    int row = blockIdx.x;
    const float* xr = x + (size_t)row * K;
    float ss = 0.f;
    int nvec = K / 4;
    const float4* xv = (const float4*)xr;
    for (int c = threadIdx.x; c < nvec; c += blockDim.x) {
        float4 v = xv[c];
        ss += v.x * v.x + v.y * v.y + v.z * v.z + v.w * v.w;
    }
    __shared__ float red[32];
    for (int off = 16; off > 0; off >>= 1) ss += __shfl_xor_sync(0xffffffffu, ss, off);
    int lane = threadIdx.x & 31, wid = threadIdx.x >> 5;
    if (lane == 0) red[wid] = ss;
    __syncthreads();
    int nwarp = blockDim.x >> 5;
    if (wid == 0) {
        float t = (lane < nwarp) ? red[lane] : 0.f;
        for (int off = 16; off > 0; off >>= 1) t += __shfl_xor_sync(0xffffffffu, t, off);
        if (lane == 0) red[0] = t;
    }
    __syncthreads();
    float inv = rsqrtf(red[0] / (float)K + EPS);

    for (int c = threadIdx.x; c < K / 2; c += blockDim.x) {
        int k = 2 * c;
        __half2 h;
        h.x = __float2half_rn(xr[k] * inv * w[k]);
        h.y = __float2half_rn(xr[k + 1] * inv * w[k + 1]);
        ((__half2*)(o + (size_t)row * K))[c] = h;
    }
}

// RoPE Q (reads fp16 qkv)
__global__ void rope_q_kernel(const __half* __restrict__ x, __half* __restrict__ o)
{
    int row = blockIdx.x;
    int b = row >> 11, s = row & 2047;
    int t = threadIdx.x;
    int h = t >> 5, i = t & 31;
    float inv_freq = powf(10000.0f, -(float)(2 * i) / 64.0f);
    float ang = (float)s * inv_freq;
    float c, sn;
    __sincosf(ang, &sn, &c);
    const __half* p = x + (size_t)row * 3072 + h * HD;
    float x1 = __half2float(p[i]), x2 = __half2float(p[i + 32]);
    size_t dst = ((size_t)(b * NH + h) * SEQ + s) * 64;
    o[dst + i]      = __float2half_rn((x1 * c - x2 * sn) * 0.125f);
    o[dst + i + 32] = __float2half_rn((x2 * c + x1 * sn) * 0.125f);
}

// RoPE K (reads fp16 qkv)
__global__ void rope_k_kernel(const __half* __restrict__ x, __half* __restrict__ o)
{
    int row = blockIdx.x;
    int b = row >> 11, s = row & 2047;
    int t = threadIdx.x;
    int h = t >> 5, i = t & 31;
    float inv_freq = powf(10000.0f, -(float)(2 * i) / 64.0f);
    float ang = (float)s * inv_freq;
    float c, sn;
    __sincosf(ang, &sn, &c);
    const __half* p = x + (size_t)row * 3072 + 2048 + h * HD;
    float x1 = __half2float(p[i]), x2 = __half2float(p[i + 32]);
    size_t dst = ((size_t)(b * NKVH + h) * SEQ + s) * 64;
    o[dst + i]      = __float2half_rn(x1 * c - x2 * sn);
    o[dst + i + 32] = __float2half_rn(x2 * c + x1 * sn);
}

// V transpose (reads fp16 qkv)
__global__ void vt_kernel(const __half* __restrict__ v, __half* __restrict__ oT)
{
    __shared__ __half t[32][34];
    int s0 = blockIdx.x * 32, d0 = blockIdx.y * 32;
    int bz = blockIdx.z;
    int b = bz >> 3, kvh = bz & 7;
    int tx = threadIdx.x, ty = threadIdx.y;
    for (int sy = ty; sy < 32; sy += 8)
        t[sy][tx] = v[(size_t)(b * SEQ + s0 + sy) * 3072 + 2560 + kvh * 64 + d0 + tx];
    __syncthreads();
    for (int dy = ty; dy < 32; dy += 8)
        oT[((size_t)bz * 64 + d0 + dy) * SEQ + s0 + tx] = t[tx][dy];
}

// ---------------- HMMA GEMM: 128x256 tile, BK=32, 4-stage ----------------
#define APITCH 80
#define A_MAT  10240
#define B_MAT  20480
#define STG_SZ (A_MAT + B_MAT)
#define GSMEM  (4 * STG_SZ)

template<int EPI>
__global__ void __launch_bounds__(256, 1)
hmma_gemm_kernel(const __half* __restrict__ A, const __half* __restrict__ B,
                 const float* __restrict__ RES,
                 float* __restrict__ C, __half* __restrict__ OH, int N, int K)
{
    extern __shared__ char sm[];
    uint32_t smb = smem_u32(sm);
    int tid = threadIdx.x, lane = tid & 31, wid = tid >> 5;
    int wm = wid & 3, wn = wid >> 2;
    int bm = blockIdx.y, bn = blockIdx.x;
    int NKT = K / 32;

    const __half* gA = A + (size_t)bm * 128 * K;
    const __half* gB = B + (size_t)bn * 256 * K;

    int rbase = tid >> 2;
    int ch = tid & 3;

    auto issue = [&](int st, int kt) {
        uint32_t base = smb + st * STG_SZ;
        int koff = kt * 32 + ch * 8;
#pragma unroll
        for (int u = 0; u < 2; u++) {
            int r = rbase + u * 64;
            cpa16(base + r * APITCH + ch * 16, gA + (size_t)r * K + koff);
        }
        uint32_t bB = base + A_MAT;
#pragma unroll
        for (int u = 0; u < 4; u++) {
            int r = rbase + u * 64;
            cpa16(bB + r * APITCH + ch * 16, gB + (size_t)r * K + koff);
        }
        cpa_commit();
    };

    float acc[2][16][4];
#pragma unroll
    for (int s = 0; s < 2; s++)
#pragma unroll
        for (int t = 0; t < 16; t++)
#pragma unroll
            for (int j = 0; j < 4; j++) acc[s][t][j] = 0.f;

    issue(0, 0);
    issue(1, 1);
    issue(2, 2);

    int a_row = wm * 32 + (lane & 15);
    int a_kb  = (lane >> 4) * 16;
    int b_ro  = ((lane >> 4) << 3) + (lane & 7);
    int b_kb  = ((lane >> 3) & 1) * 16;

    for (int kt = 0; kt < NKT; kt++) {
        int st = kt & 3;
        asm volatile("cp.async.wait_group 2;" ::: "memory");
        __syncthreads();
        if (kt + 3 < NKT) issue((kt + 3) & 3, kt + 3);
        else cpa_commit();

        uint32_t sA = smb + st * STG_SZ;
        uint32_t sB = sA + A_MAT;

#pragma unroll
        for (int ks = 0; ks < 2; ks++) {
            int kB = ks * 32;
            uint32_t a4[2][4];
            ldsm4(a4[0], sA + (a_row)      * APITCH + kB + a_kb);
            ldsm4(a4[1], sA + (a_row + 16) * APITCH + kB + a_kb);
#pragma unroll
            for (int gi = 0; gi < 8; gi++) {
                int brow = wn * 128 + gi * 16 + b_ro;
                uint32_t b4[4];
                ldsm4(b4, sB + brow * APITCH + kB + b_kb);
#pragma unroll
                for (int t = 0; t < 2; t++) {
                    const uint32_t* bp = &b4[t * 2];
#pragma unroll
                    for (int sub = 0; sub < 2; sub++)
                        mma_f16(acc[sub][gi * 2 + t], a4[sub], bp);
                }
            }
        }
    }

    // epilogue
#pragma unroll
    for (int sub = 0; sub < 2; sub++) {
        int row0 = bm * 128 + wm * 32 + sub * 16 + (lane >> 2);
        if (EPI == 4) {
#pragma unroll
            for (int j = 0; j < 8; j++) {
                int col = bn * 128 + wn * 64 + j * 8 + (lane & 3) * 2;
                size_t o0 = (size_t)row0 * FF + col;
                size_t o1 = o0 + (size_t)8 * FF;
                float* g = acc[sub][2 * j];
                float* u = acc[sub][2 * j + 1];
                __half2 H0, H1;
                H0.x = __float2half_rn(fsilu(g[0]) * u[0]);
                H0.y = __float2half_rn(fsilu(g[1]) * u[1]);
                H1.x = __float2half_rn(fsilu(g[2]) * u[2]);
                H1.y = __float2half_rn(fsilu(g[3]) * u[3]);
                *(__half2*)(OH + o0) = H0;
                *(__half2*)(OH + o1) = H1;
            }
        } else {
#pragma unroll
            for (int t = 0; t < 16; t++) {
                int col = bn * 256 + wn * 128 + t * 8 + (lane & 3) * 2;
                size_t o0 = (size_t)row0 * N + col;
                size_t o1 = o0 + (size_t)8 * N;
                if (EPI == 3) {
                    __half2 H0, H1;
                    H0.x = __float2half_rn(acc[sub][t][0]);
                    H0.y = __float2half_rn(acc[sub][t][1]);
                    H1.x = __float2half_rn(acc[sub][t][2]);
                    H1.y = __float2half_rn(acc[sub][t][3]);
                    *(__half2*)(OH + o0) = H0;
                    *(__half2*)(OH + o1) = H1;
                } else {
                    float2 v0 = make_float2(acc[sub][t][0], acc[sub][t][1]);
                    float2 v1 = make_float2(acc[sub][t][2], acc[sub][t][3]);
                    if (EPI == 1) {
                        float2 r0 = *(const float2*)(RES + o0);
                        float2 r1 = *(const float2*)(RES + o1);
                        v0.x += r0.x; v0.y += r0.y;
                        v1.x += r1.x; v1.y += r1.y;
                    }
                    *(float2*)(C + o0) = v0;
                    *(float2*)(C + o1) = v1;
                }
            }
        }
    }
}

// ---------------- tensor-core causal attention: Br=128, Bc=64, 256 threads ----------------
#define AT_PITCH 144
#define AT_KMAT  (64 * AT_PITCH)       // 9216
#define AT_QMAT  (128 * AT_PITCH)      // 18432
#define AT_Q   0
#define AT_KV  (AT_QMAT)
#define AT_SMEM (AT_QMAT + 2 * 2 * AT_KMAT)   // 55296

__global__ void __launch_bounds__(256)
attn_mma_kernel(const __half* __restrict__ qq, const __half* __restrict__ kk,
                const __half* __restrict__ vt, __half* __restrict__ OH)
{
    extern __shared__ char sm[];
    uint32_t smb = smem_u32(sm);
    int qt = blockIdx.x, h = blockIdx.y, b = blockIdx.z;   // qt: 128-row block
    int kvh = h >> 2;
    int tid = threadIdx.x, lane = tid & 31, w = tid >> 5;  // 8 warps, 16 rows each
    int q0 = qt * 128;
    int KT = 2 * qt + 1;                                    // last k-tile index

    const __half* Qp = qq + ((size_t)(b * NH + h) * SEQ + q0) * 64;
    const __half* Kp = kk + ((size_t)(b * NKVH + kvh) * SEQ) * 64;
    const __half* Vp = vt + ((size_t)(b * NKVH + kvh) * 64) * SEQ;

    auto issue_kv = [&](int st, int kt) {
        int k0 = kt * 64;
        uint32_t base = smb + AT_KV + st * (2 * AT_KMAT);
#pragma unroll
        for (int it = 0; it < 2; it++) {
            int idx = it * 256 + tid;
            int r = idx >> 3, ch = idx & 7;
            cpa16(base + r * AT_PITCH + ch * 16,           Kp + (size_t)(k0 + r) * 64 + ch * 8);
            cpa16(base + AT_KMAT + r * AT_PITCH + ch * 16, Vp + (size_t)r * SEQ + k0 + ch * 8);
        }
        cpa_commit();
    };

    // load Q (128 rows)
#pragma unroll
    for (int it = 0; it < 4; it++) {
        int idx = it * 256 + tid;
        int r = idx >> 3, ch = idx & 7;
        cpa16(smb + AT_Q + r * AT_PITCH + ch * 16, Qp + (size_t)r * 64 + ch * 8);
    }
    cpa_commit();
    asm volatile("cp.async.wait_group 0;" ::: "memory");
    __syncthreads();

    int r0 = lane >> 2, cq = lane & 3;
    int a_row = w * 16 + (lane & 15);
    int a_kb  = (lane >> 4) * 16;
    int b_ro  = ((lane >> 4) << 3) + (lane & 7);
    int b_kb  = ((lane >> 3) & 1) * 16;

    uint32_t qf[4][4];
#pragma unroll
    for (int kc = 0; kc < 4; kc++)
        ldsm4(qf[kc], smb + AT_Q + a_row * AT_PITCH + kc * 32 + a_kb);

    issue_kv(0, 0);

    float m0 = -1e30f, m1 = -1e30f, l0 = 0.f, l1 = 0.f;
    float ao[8][4];
#pragma unroll
    for (int nt = 0; nt < 8; nt++)
#pragma unroll
        for (int j = 0; j < 4; j++) ao[nt][j] = 0.f;

    int qr0g = q0 + w * 16 + r0;       // global row of this thread's first row
    int qr1g = qr0g + 8;

    for (int kt = 0; kt <= KT; kt++) {
        int st = kt & 1;
        asm volatile("cp.async.wait_group 0;" ::: "memory");
        __syncthreads();
        if (kt < KT) issue_kv((kt + 1) & 1, kt + 1);

        uint32_t sK = smb + AT_KV + st * (2 * AT_KMAT);
        uint32_t sV = sK + AT_KMAT;

        float sc[8][4];
#pragma unroll
        for (int nt = 0; nt < 8; nt++)
#pragma unroll
            for (int j = 0; j < 4; j++) sc[nt][j] = 0.f;

#pragma unroll
        for (int kc = 0; kc < 4; kc++) {
#pragma unroll
            for (int gi = 0; gi < 4; gi++) {
                uint32_t k4[4];
                ldsm4(k4, sK + (gi * 16 + b_ro) * AT_PITCH + kc * 32 + b_kb);
#pragma unroll
                for (int t = 0; t < 2; t++)
                    mma_f16(sc[gi * 2 + t], qf[kc], &k4[t * 2]);
            }
        }

        // causal mask (only diagonal-crossing tiles: kt >= 2*qt)
        if (kt >= 2 * qt) {
            int kbase = kt * 64;
#pragma unroll
            for (int nt = 0; nt < 8; nt++) {
                int col = kbase + nt * 8 + cq * 2;
                if (col     > qr0g) sc[nt][0] = -1e30f;
                if (col + 1 > qr0g) sc[nt][1] = -1e30f;
                if (col     > qr1g) sc[nt][2] = -1e30f;
                if (col + 1 > qr1g) sc[nt][3] = -1e30f;
            }
        }

        float tm0 = -1e30f, tm1 = -1e30f;
#pragma unroll
        for (int nt = 0; nt < 8; nt++) {
            tm0 = fmaxf(tm0, fmaxf(sc[nt][0], sc[nt][1]));
            tm1 = fmaxf(tm1, fmaxf(sc[nt][2], sc[nt][3]));
        }
        tm0 = fmaxf(tm0, __shfl_xor_sync(0xffffffffu, tm0, 1));
        tm0 = fmaxf(tm0, __shfl_xor_sync(0xffffffffu, tm0, 2));
        tm1 = fmaxf(tm1, __shfl_xor_sync(0xffffffffu, tm1, 1));
        tm1 = fmaxf(tm1, __shfl_xor_sync(0xffffffffu, tm1, 2));
        float mn0 = fmaxf(m0, tm0), mn1 = fmaxf(m1, tm1);
        float cr0 = fexp2((m0 - mn0) * L2E);
        float cr1 = fexp2((m1 - mn1) * L2E);
        float rs0 = 0.f, rs1 = 0.f;
#pragma unroll
        for (int nt = 0; nt < 8; nt++) {
            sc[nt][0] = fexp2((sc[nt][0] - mn0) * L2E);
            sc[nt][1] = fexp2((sc[nt][1] - mn0) * L2E);
            sc[nt][2] = fexp2((sc[nt][2] - mn1) * L2E);
            sc[nt][3] = fexp2((sc[nt][3] - mn1) * L2E);
            rs0 += sc[nt][0] + sc[nt][1];
            rs1 += sc[nt][2] + sc[nt][3];
        }
        rs0 += __shfl_xor_sync(0xffffffffu, rs0, 1);
        rs0 += __shfl_xor_sync(0xffffffffu, rs0, 2);
        rs1 += __shfl_xor_sync(0xffffffffu, rs1, 1);
        rs1 += __shfl_xor_sync(0xffffffffu, rs1, 2);
        l0 = l0 * cr0 + rs0;
        l1 = l1 * cr1 + rs1;
        m0 = mn0; m1 = mn1;
#pragma unroll
        for (int nt = 0; nt < 8; nt++) {
            ao[nt][0] *= cr0; ao[nt][1] *= cr0;
            ao[nt][2] *= cr1; ao[nt][3] *= cr1;
        }

#pragma unroll
        for (int j = 0; j < 4; j++) {
            uint32_t pa[4];
#pragma unroll
            for (int u = 0; u < 2; u++) {
                __half2 H0 = __floats2half2_rn(sc[2 * j + u][0], sc[2 * j + u][1]);
                __half2 H1 = __floats2half2_rn(sc[2 * j + u][2], sc[2 * j + u][3]);
                pa[2 * u + 0] = *(uint32_t*)&H0;
                pa[2 * u + 1] = *(uint32_t*)&H1;
            }
#pragma unroll
            for (int gi = 0; gi < 4; gi++) {
                uint32_t v4[4];
                ldsm4(v4, sV + (gi * 16 + b_ro) * AT_PITCH + j * 32 + b_kb);
#pragma unroll
                for (int t = 0; t < 2; t++)
                    mma_f16(ao[gi * 2 + t], pa, &v4[t * 2]);
            }
        }
    }

    float i0 = 1.f / l0, i1 = 1.f / l1;
#pragma unroll
    for (int nt = 0; nt < 8; nt++) {
        int col = h * 64 + nt * 8 + cq * 2;
        size_t oA = ((size_t)(b * SEQ) + qr0g) * 2048 + col;
        size_t oB = ((size_t)(b * SEQ) + qr1g) * 2048 + col;
        *(__half2*)(OH + oA) = __floats2half2_rn(ao[nt][0] * i0, ao[nt][1] * i0);
        *(__half2*)(OH + oB) = __floats2half2_rn(ao[nt][2] * i1, ao[nt][3] * i1);
    }
}

// ---------------- host launch ----------------
extern "C" void kernel_launch(void* const* d_in, const int* in_sizes, int n_in,
                              void* d_out, int out_size)
{
    const float* hidden  = (const float*)d_in[0];
    const float* norm1_w = (const float*)d_in[2];
    const float* wq      = (const float*)d_in[3];
    const float* wk      = (const float*)d_in[4];
    const float* wv      = (const float*)d_in[5];
    const float* wo      = (const float*)d_in[6];
    const float* norm2_w = (const float*)d_in[7];
    const float* w_gate  = (const float*)d_in[8];
    const float* w_up    = (const float*)d_in[9];
    const float* w_down  = (const float*)d_in[10];
    float* out = (float*)d_out;

    float *res2;
    __half *qkvh, *ab, *wpool, *qb, *kbuf, *vtb, *mbuf;
    cudaGetSymbolAddress((void**)&res2, g_res2);
    cudaGetSymbolAddress((void**)&qkvh, g_qkvh);
    cudaGetSymbolAddress((void**)&mbuf, g_m);
    cudaGetSymbolAddress((void**)&ab,   g_a);
    cudaGetSymbolAddress((void**)&wpool, g_w);
    cudaGetSymbolAddress((void**)&qb,   g_q);
    cudaGetSymbolAddress((void**)&kbuf, g_k);
    cudaGetSymbolAddress((void**)&vtb,  g_vt);

    const size_t OQKV = 0;
    const size_t OWO  = 6ull * MEG;
    const size_t OGU  = 10ull * MEG;
    const size_t OWD  = 42ull * MEG;

    cudaFuncSetAttribute(hmma_gemm_kernel<1>, cudaFuncAttributeMaxDynamicSharedMemorySize, GSMEM);
    cudaFuncSetAttribute(hmma_gemm_kernel<3>, cudaFuncAttributeMaxDynamicSharedMemorySize, GSMEM);
    cudaFuncSetAttribute(hmma_gemm_kernel<4>, cudaFuncAttributeMaxDynamicSharedMemorySize, GSMEM);
    cudaFuncSetAttribute(attn_mma_kernel, cudaFuncAttributeMaxDynamicSharedMemorySize, AT_SMEM);

    // ---- weight conversions ----
    convT_kernel<<<dim3(32, 32), 256>>>(wq, wpool + OQKV, 2048, 2048);
    convT_kernel<<<dim3(8, 32), 256>>>(wk, wpool + OQKV + 2048ull * 2048, 2048, 512);
    convT_kernel<<<dim3(8, 32), 256>>>(wv, wpool + OQKV + 2560ull * 2048, 2048, 512);
    convT_kernel<<<dim3(32, 32), 256>>>(wo, wpool + OWO, 2048, 2048);
    convT_gu_kernel<<<dim3(128, 32), 256>>>(w_gate, w_up, wpool + OGU, 2048);
    convT_kernel<<<dim3(32, 128), 256>>>(w_down, wpool + OWD, 8192, 2048);

    // ---- 1. rmsnorm1 -> fp16 ----
    rmsnorm_h_kernel<<<ROWS, 256>>>(hidden, norm1_w, ab, HID);

    // ---- 2. fused QKV GEMM -> qkv fp16 ----
    hmma_gemm_kernel<3><<<dim3(3072 / 256, ROWS / 128), 256, GSMEM>>>(
        ab, wpool + OQKV, nullptr, nullptr, qkvh, 3072, 2048);

    // ---- 3. RoPE Q/K + V transpose ----
    rope_q_kernel<<<ROWS, NH * 32>>>(qkvh, qb);
    rope_k_kernel<<<ROWS, NKVH * 32>>>(qkvh, kbuf);
    vt_kernel<<<dim3(SEQ / 32, 2, NB * NKVH), dim3(32, 8)>>>(qkvh, vtb);

    // ---- 4. attention (Br=128) -> ctx fp16 (ab) ----
    attn_mma_kernel<<<dim3(SEQ / 128, NH, NB), 256, AT_SMEM>>>(qb, kbuf, vtb, ab);

    // ---- 5. output projection + residual -> res2 fp32 ----
    hmma_gemm_kernel<1><<<dim3(2048 / 256, ROWS / 128), 256, GSMEM>>>(
        ab, wpool + OWO, hidden, res2, nullptr, 2048, 2048);

    // ---- 6. rmsnorm2 -> fp16 ----
    rmsnorm_h_kernel<<<ROWS, 256>>>(res2, norm2_w, ab, HID);

    // ---- 7. fused gate+up GEMM + silu-mul -> fp16 (mbuf) ----
    hmma_gemm_kernel<4><<<dim3(2 * FF / 256, ROWS / 128), 256, GSMEM>>>(
        ab, wpool + OGU, nullptr, nullptr, mbuf, FF, 2048);

    // ---- 8. down projection + residual -> out ----
    hmma_gemm_kernel<1><<<dim3(2048 / 256, ROWS / 128), 256, GSMEM>>>(
        mbuf, wpool + OWD, res2, out, nullptr, 2048, 8192);
}

// round 15
// speedup vs baseline: 1.0157x; 1.0157x over previous
#include <cuda_runtime.h>
#include <cuda_bf16.h>
#include <cuda_fp16.h>
#include <math.h>
#include <stdint.h>

// ---------------- problem constants ----------------
#define HID   2048
#define NH    32
#define NKVH  8
#define HD    64
#define FF    8192
#define SEQ   2048
#define NB    2
#define ROWS  4096
#define EPS   1e-6f
#define MEG   (1024*1024)
#define L2E   1.4426950408889634f
#define NT    (SEQ / 64)

// ---------------- scratch (device globals; no allocs allowed) ----------------
__device__ float  g_res2[(size_t)ROWS * 2048];
__device__ __half g_qkvh[(size_t)ROWS * 3072];
__device__ __half g_m  [(size_t)ROWS * FF];

__device__ __half g_a  [(size_t)ROWS * HID];
__device__ __half g_w  [(size_t)58 * MEG];

__device__ __half g_q  [(size_t)ROWS * 2048];
__device__ __half g_k  [(size_t)ROWS * 512];
__device__ __half g_vt [(size_t)ROWS * 512];

// ---------------- helpers ----------------
__device__ __forceinline__ uint32_t smem_u32(const void* p) {
    uint32_t a;
    asm("{ .reg .u64 t; cvta.to.shared.u64 t, %1; cvt.u32.u64 %0, t; }" : "=r"(a) : "l"(p));
    return a;
}

__device__ __forceinline__ void cpa16(uint32_t dst, const void* src) {
    asm volatile("cp.async.cg.shared.global [%0], [%1], 16;" :: "r"(dst), "l"(src));
}
__device__ __forceinline__ void cpa_commit() {
    asm volatile("cp.async.commit_group;" ::: "memory");
}

__device__ __forceinline__ void ldsm4(uint32_t* r, uint32_t addr) {
    asm volatile("ldmatrix.sync.aligned.m8n8.x4.shared.b16 {%0,%1,%2,%3}, [%4];"
        : "=r"(r[0]), "=r"(r[1]), "=r"(r[2]), "=r"(r[3]) : "r"(addr));
}

__device__ __forceinline__ void mma_f16(float* c, const uint32_t* a, const uint32_t* b) {
    asm volatile("mma.sync.aligned.m16n8k16.row.col.f32.f16.f16.f32 "
        "{%0,%1,%2,%3}, {%4,%5,%6,%7}, {%8,%9}, {%0,%1,%2,%3};"
        : "+f"(c[0]), "+f"(c[1]), "+f"(c[2]), "+f"(c[3])
        : "r"(a[0]), "r"(a[1]), "r"(a[2]), "r"(a[3]), "r"(b[0]), "r"(b[1]));
}

__device__ __forceinline__ float fexp2(float z) {
    z = fminf(fmaxf(z, -126.f), 126.f);
    float sh = z + 12582912.f;
    float zi = sh - 12582912.f;
    float f = z - zi;
    float p = 0.0013333558f;
    p = p * f + 0.0096181291f;
    p = p * f + 0.0555041087f;
    p = p * f + 0.2402265070f;
    p = p * f + 0.6931471806f;
    p = p * f + 1.0f;
    int ei = __float_as_int(sh) - 0x4B400000;
    return p * __int_as_float((ei + 127) << 23);
}

__device__ __forceinline__ float fsilu(float x) {
    return x / (1.f + fexp2(-x * L2E));
}

// ---------------- converters ----------------
__global__ void convT_kernel(const float* __restrict__ W,
                             __half* __restrict__ wT, int K, int N)
{
    __shared__ float t[64][67];
    int n0 = blockIdx.x * 64, k0 = blockIdx.y * 64;
    int tx = threadIdx.x & 31, ty = threadIdx.x >> 5;
    int cx = threadIdx.x & 15;
    int ry = threadIdx.x >> 4;
    for (int ky = ry; ky < 64; ky += 16) {
        float4 v = *(const float4*)(W + (size_t)(k0 + ky) * N + n0 + cx * 4);
        t[ky][cx * 4 + 0] = v.x; t[ky][cx * 4 + 1] = v.y;
        t[ky][cx * 4 + 2] = v.z; t[ky][cx * 4 + 3] = v.w;
    }
    __syncthreads();
    for (int ny = ty; ny < 64; ny += 8) {
        __half2 h;
        h.x = __float2half_rn(t[2 * tx][ny]);
        h.y = __float2half_rn(t[2 * tx + 1][ny]);
        *(__half2*)(wT + (size_t)(n0 + ny) * K + k0 + 2 * tx) = h;
    }
}

__global__ void convT_gu_kernel(const float* __restrict__ G,
                                const float* __restrict__ U,
                                __half* __restrict__ wT, int K)
{
    __shared__ float tg[64][67];
    __shared__ float tu[64][67];
    int n0 = blockIdx.x * 64, k0 = blockIdx.y * 64;
    int tx = threadIdx.x & 31, ty = threadIdx.x >> 5;
    int cx = threadIdx.x & 15;
    int ry = threadIdx.x >> 4;
    for (int ky = ry; ky < 64; ky += 16) {
        float4 v = *(const float4*)(G + (size_t)(k0 + ky) * FF + n0 + cx * 4);
        tg[ky][cx * 4 + 0] = v.x; tg[ky][cx * 4 + 1] = v.y;
        tg[ky][cx * 4 + 2] = v.z; tg[ky][cx * 4 + 3] = v.w;
        float4 u = *(const float4*)(U + (size_t)(k0 + ky) * FF + n0 + cx * 4);
        tu[ky][cx * 4 + 0] = u.x; tu[ky][cx * 4 + 1] = u.y;
        tu[ky][cx * 4 + 2] = u.z; tu[ky][cx * 4 + 3] = u.w;
    }
    __syncthreads();
    for (int ny = ty; ny < 64; ny += 8) {
        int n = n0 + ny;
        size_t rowG = (size_t)((n >> 7) * 256 + ((n >> 6) & 1) * 128 + ((n >> 3) & 7) * 16 + (n & 7));
        __half2 h;
        h.x = __float2half_rn(tg[2 * tx][ny]);
        h.y = __float2half_rn(tg[2 * tx + 1][ny]);
        *(__half2*)(wT + rowG * K + k0 + 2 * tx) = h;
        h.x = __float2half_rn(tu[2 * tx][ny]);
        h.y = __float2half_rn(tu[2 * tx + 1][ny]);
        *(__half2*)(wT + (rowG + 8) * K + k0 + 2 * tx) = h;
    }
}

// RMSNorm -> fp16
__global__ void rmsnorm_h_kernel(const float* __restrict__ x,
                                 const float* __restrict__ w,
                                 __half* __restrict__ o, int K)
{
    int row = blockIdx.x;
    const float* xr = x + (size_t)row * K;
    float ss = 0.f;
    int nvec = K / 4;
    const float4* xv = (const float4*)xr;
    for (int c = threadIdx.x; c < nvec; c += blockDim.x) {
        float4 v = xv[c];
        ss += v.x * v.x + v.y * v.y + v.z * v.z + v.w * v.w;
    }
    __shared__ float red[32];
    for (int off = 16; off > 0; off >>= 1) ss += __shfl_xor_sync(0xffffffffu, ss, off);
    int lane = threadIdx.x & 31, wid = threadIdx.x >> 5;
    if (lane == 0) red[wid] = ss;
    __syncthreads();
    int nwarp = blockDim.x >> 5;
    if (wid == 0) {
        float t = (lane < nwarp) ? red[lane] : 0.f;
        for (int off = 16; off > 0; off >>= 1) t += __shfl_xor_sync(0xffffffffu, t, off);
        if (lane == 0) red[0] = t;
    }
    __syncthreads();
    float inv = rsqrtf(red[0] / (float)K + EPS);

    for (int c = threadIdx.x; c < K / 2; c += blockDim.x) {
        int k = 2 * c;
        __half2 h;
        h.x = __float2half_rn(xr[k] * inv * w[k]);
        h.y = __float2half_rn(xr[k + 1] * inv * w[k + 1]);
        ((__half2*)(o + (size_t)row * K))[c] = h;
    }
}

// RoPE Q (reads fp16 qkv)
__global__ void rope_q_kernel(const __half* __restrict__ x, __half* __restrict__ o)
{
    int row = blockIdx.x;
    int b = row >> 11, s = row & 2047;
    int t = threadIdx.x;
    int h = t >> 5, i = t & 31;
    float inv_freq = powf(10000.0f, -(float)(2 * i) / 64.0f);
    float ang = (float)s * inv_freq;
    float c, sn;
    __sincosf(ang, &sn, &c);
    const __half* p = x + (size_t)row * 3072 + h * HD;
    float x1 = __half2float(p[i]), x2 = __half2float(p[i + 32]);
    size_t dst = ((size_t)(b * NH + h) * SEQ + s) * 64;
    o[dst + i]      = __float2half_rn((x1 * c - x2 * sn) * 0.125f);
    o[dst + i + 32] = __float2half_rn((x2 * c + x1 * sn) * 0.125f);
}

// RoPE K (reads fp16 qkv)
__global__ void rope_k_kernel(const __half* __restrict__ x, __half* __restrict__ o)
{
    int row = blockIdx.x;
    int b = row >> 11, s = row & 2047;
    int t = threadIdx.x;
    int h = t >> 5, i = t & 31;
    float inv_freq = powf(10000.0f, -(float)(2 * i) / 64.0f);
    float ang = (float)s * inv_freq;
    float c, sn;
    __sincosf(ang, &sn, &c);
    const __half* p = x + (size_t)row * 3072 + 2048 + h * HD;
    float x1 = __half2float(p[i]), x2 = __half2float(p[i + 32]);
    size_t dst = ((size_t)(b * NKVH + h) * SEQ + s) * 64;
    o[dst + i]      = __float2half_rn(x1 * c - x2 * sn);
    o[dst + i + 32] = __float2half_rn(x2 * c + x1 * sn);
}

// V transpose (reads fp16 qkv)
__global__ void vt_kernel(const __half* __restrict__ v, __half* __restrict__ oT)
{
    __shared__ __half t[32][34];
    int s0 = blockIdx.x * 32, d0 = blockIdx.y * 32;
    int bz = blockIdx.z;
    int b = bz >> 3, kvh = bz & 7;
    int tx = threadIdx.x, ty = threadIdx.y;
    for (int sy = ty; sy < 32; sy += 8)
        t[sy][tx] = v[(size_t)(b * SEQ + s0 + sy) * 3072 + 2560 + kvh * 64 + d0 + tx];
    __syncthreads();
    for (int dy = ty; dy < 32; dy += 8)
        oT[((size_t)bz * 64 + d0 + dy) * SEQ + s0 + tx] = t[tx][dy];
}

// ---------------- HMMA GEMM: 128x256 tile, BK=32, 3-stage (2 CTAs/SM) ----------------
#define APITCH 80
#define A_MAT  10240
#define B_MAT  20480
#define STG_SZ (A_MAT + B_MAT)
#define GSMEM  (3 * STG_SZ)            // 92160 -> 2 CTAs/SM

template<int EPI>
__global__ void __launch_bounds__(256, 2)
hmma_gemm_kernel(const __half* __restrict__ A, const __half* __restrict__ B,
                 const float* __restrict__ RES,
                 float* __restrict__ C, __half* __restrict__ OH, int N, int K)
{
    extern __shared__ char sm[];
    uint32_t smb = smem_u32(sm);
    int tid = threadIdx.x, lane = tid & 31, wid = tid >> 5;
    int wm = wid & 3, wn = wid >> 2;
    int bm = blockIdx.y, bn = blockIdx.x;
    int NKT = K / 32;

    const __half* gA = A + (size_t)bm * 128 * K;
    const __half* gB = B + (size_t)bn * 256 * K;

    int rbase = tid >> 2;
    int ch = tid & 3;

    auto issue = [&](int st, int kt) {
        uint32_t base = smb + st * STG_SZ;
        int koff = kt * 32 + ch * 8;
#pragma unroll
        for (int u = 0; u < 2; u++) {
            int r = rbase + u * 64;
            cpa16(base + r * APITCH + ch * 16, gA + (size_t)r * K + koff);
        }
        uint32_t bB = base + A_MAT;
#pragma unroll
        for (int u = 0; u < 4; u++) {
            int r = rbase + u * 64;
            cpa16(bB + r * APITCH + ch * 16, gB + (size_t)r * K + koff);
        }
        cpa_commit();
    };

    float acc[2][16][4];
#pragma unroll
    for (int s = 0; s < 2; s++)
#pragma unroll
        for (int t = 0; t < 16; t++)
#pragma unroll
            for (int j = 0; j < 4; j++) acc[s][t][j] = 0.f;

    issue(0, 0);
    issue(1, 1);

    int a_row = wm * 32 + (lane & 15);
    int a_kb  = (lane >> 4) * 16;
    int b_ro  = ((lane >> 4) << 3) + (lane & 7);
    int b_kb  = ((lane >> 3) & 1) * 16;

    // 3-stage: 2 groups pending before each wait; wait<=1 drains group kt.
    // The __syncthreads after the wait guarantees compute(kt-1) done in all
    // warps, so issuing kt+2 into buffer (kt+2)%3 == (kt-1)%3 is safe.
    for (int kt = 0; kt < NKT; kt++) {
        int st = kt % 3;
        asm volatile("cp.async.wait_group 1;" ::: "memory");
        __syncthreads();
        if (kt + 2 < NKT) issue((kt + 2) % 3, kt + 2);
        else cpa_commit();

        uint32_t sA = smb + st * STG_SZ;
        uint32_t sB = sA + A_MAT;

#pragma unroll
        for (int ks = 0; ks < 2; ks++) {
            int kB = ks * 32;
            uint32_t a4[2][4];
            ldsm4(a4[0], sA + (a_row)      * APITCH + kB + a_kb);
            ldsm4(a4[1], sA + (a_row + 16) * APITCH + kB + a_kb);
#pragma unroll
            for (int gi = 0; gi < 8; gi++) {
                int brow = wn * 128 + gi * 16 + b_ro;
                uint32_t b4[4];
                ldsm4(b4, sB + brow * APITCH + kB + b_kb);
#pragma unroll
                for (int t = 0; t < 2; t++) {
                    const uint32_t* bp = &b4[t * 2];
#pragma unroll
                    for (int sub = 0; sub < 2; sub++)
                        mma_f16(acc[sub][gi * 2 + t], a4[sub], bp);
                }
            }
        }
    }

    // epilogue
#pragma unroll
    for (int sub = 0; sub < 2; sub++) {
        int row0 = bm * 128 + wm * 32 + sub * 16 + (lane >> 2);
        if (EPI == 4) {
#pragma unroll
            for (int j = 0; j < 8; j++) {
                int col = bn * 128 + wn * 64 + j * 8 + (lane & 3) * 2;
                size_t o0 = (size_t)row0 * FF + col;
                size_t o1 = o0 + (size_t)8 * FF;
                float* g = acc[sub][2 * j];
                float* u = acc[sub][2 * j + 1];
                __half2 H0, H1;
                H0.x = __float2half_rn(fsilu(g[0]) * u[0]);
                H0.y = __float2half_rn(fsilu(g[1]) * u[1]);
                H1.x = __float2half_rn(fsilu(g[2]) * u[2]);
                H1.y = __float2half_rn(fsilu(g[3]) * u[3]);
                *(__half2*)(OH + o0) = H0;
                *(__half2*)(OH + o1) = H1;
            }
        } else {
#pragma unroll
            for (int t = 0; t < 16; t++) {
                int col = bn * 256 + wn * 128 + t * 8 + (lane & 3) * 2;
                size_t o0 = (size_t)row0 * N + col;
                size_t o1 = o0 + (size_t)8 * N;
                if (EPI == 3) {
                    __half2 H0, H1;
                    H0.x = __float2half_rn(acc[sub][t][0]);
                    H0.y = __float2half_rn(acc[sub][t][1]);
                    H1.x = __float2half_rn(acc[sub][t][2]);
                    H1.y = __float2half_rn(acc[sub][t][3]);
                    *(__half2*)(OH + o0) = H0;
                    *(__half2*)(OH + o1) = H1;
                } else {
                    float2 v0 = make_float2(acc[sub][t][0], acc[sub][t][1]);
                    float2 v1 = make_float2(acc[sub][t][2], acc[sub][t][3]);
                    if (EPI == 1) {
                        float2 r0 = *(const float2*)(RES + o0);
                        float2 r1 = *(const float2*)(RES + o1);
                        v0.x += r0.x; v0.y += r0.y;
                        v1.x += r1.x; v1.y += r1.y;
                    }
                    *(float2*)(C + o0) = v0;
                    *(float2*)(C + o1) = v1;
                }
            }
        }
    }
}

// ---------------- tensor-core causal attention (R13: single tile, 2-stage K/V) ----------------
#define AT_PITCH 144
#define AT_MAT   (64 * AT_PITCH)
#define AT_Q   0
#define AT_KV  (AT_MAT)
#define AT_SMEM (AT_MAT + 2 * 2 * AT_MAT)   // 46080

__global__ void __launch_bounds__(128)
attn_mma_kernel(const __half* __restrict__ qq, const __half* __restrict__ kk,
                const __half* __restrict__ vt, __half* __restrict__ OH)
{
    extern __shared__ char sm[];
    uint32_t smb = smem_u32(sm);
    int qt = blockIdx.x, h = blockIdx.y, b = blockIdx.z;
    int kvh = h >> 2;
    int tid = threadIdx.x, lane = tid & 31, w = tid >> 5;
    int q0 = qt * 64;

    const __half* Qp = qq + ((size_t)(b * NH + h) * SEQ + q0) * 64;
    const __half* Kp = kk + ((size_t)(b * NKVH + kvh) * SEQ) * 64;
    const __half* Vp = vt + ((size_t)(b * NKVH + kvh) * 64) * SEQ;

    auto issue_kv = [&](int st, int kt) {
        int k0 = kt * 64;
        uint32_t base = smb + AT_KV + st * (2 * AT_MAT);
#pragma unroll
        for (int it = 0; it < 4; it++) {
            int idx = it * 128 + tid;
            int r = idx >> 3, ch = idx & 7;
            cpa16(base + r * AT_PITCH + ch * 16,          Kp + (size_t)(k0 + r) * 64 + ch * 8);
            cpa16(base + AT_MAT + r * AT_PITCH + ch * 16, Vp + (size_t)r * SEQ + k0 + ch * 8);
        }
        cpa_commit();
    };

#pragma unroll
    for (int it = 0; it < 4; it++) {
        int idx = it * 128 + tid;
        int r = idx >> 3, ch = idx & 7;
        cpa16(smb + AT_Q + r * AT_PITCH + ch * 16, Qp + (size_t)r * 64 + ch * 8);
    }
    cpa_commit();
    asm volatile("cp.async.wait_group 0;" ::: "memory");
    __syncthreads();

    int r0 = lane >> 2, cq = lane & 3;
    int a_row = w * 16 + (lane & 15);
    int a_kb  = (lane >> 4) * 16;
    int b_ro  = ((lane >> 4) << 3) + (lane & 7);
    int b_kb  = ((lane >> 3) & 1) * 16;

    uint32_t qf[4][4];
#pragma unroll
    for (int kc = 0; kc < 4; kc++)
        ldsm4(qf[kc], smb + AT_Q + a_row * AT_PITCH + kc * 32 + a_kb);

    issue_kv(0, 0);

    float m0 = -1e30f, m1 = -1e30f, l0 = 0.f, l1 = 0.f;
    float ao[8][4];
#pragma unroll
    for (int nt = 0; nt < 8; nt++)
#pragma unroll
        for (int j = 0; j < 4; j++) ao[nt][j] = 0.f;

    for (int kt = 0; kt <= qt; kt++) {
        int st = kt & 1;
        asm volatile("cp.async.wait_group 0;" ::: "memory");
        __syncthreads();
        if (kt < qt) issue_kv((kt + 1) & 1, kt + 1);

        uint32_t sK = smb + AT_KV + st * (2 * AT_MAT);
        uint32_t sV = sK + AT_MAT;

        float sc[8][4];
#pragma unroll
        for (int nt = 0; nt < 8; nt++)
#pragma unroll
            for (int j = 0; j < 4; j++) sc[nt][j] = 0.f;

#pragma unroll
        for (int kc = 0; kc < 4; kc++) {
#pragma unroll
            for (int gi = 0; gi < 4; gi++) {
                uint32_t k4[4];
                ldsm4(k4, sK + (gi * 16 + b_ro) * AT_PITCH + kc * 32 + b_kb);
#pragma unroll
                for (int t = 0; t < 2; t++)
                    mma_f16(sc[gi * 2 + t], qf[kc], &k4[t * 2]);
            }
        }

        if (kt == qt) {
            int qr0 = w * 16 + r0, qr1 = qr0 + 8;
#pragma unroll
            for (int nt = 0; nt < 8; nt++) {
                int col = nt * 8 + cq * 2;
                if (col     > qr0) sc[nt][0] = -1e30f;
                if (col + 1 > qr0) sc[nt][1] = -1e30f;
                if (col     > qr1) sc[nt][2] = -1e30f;
                if (col + 1 > qr1) sc[nt][3] = -1e30f;
            }
        }

        float tm0 = -1e30f, tm1 = -1e30f;
#pragma unroll
        for (int nt = 0; nt < 8; nt++) {
            tm0 = fmaxf(tm0, fmaxf(sc[nt][0], sc[nt][1]));
            tm1 = fmaxf(tm1, fmaxf(sc[nt][2], sc[nt][3]));
        }
        tm0 = fmaxf(tm0, __shfl_xor_sync(0xffffffffu, tm0, 1));
        tm0 = fmaxf(tm0, __shfl_xor_sync(0xffffffffu, tm0, 2));
        tm1 = fmaxf(tm1, __shfl_xor_sync(0xffffffffu, tm1, 1));
        tm1 = fmaxf(tm1, __shfl_xor_sync(0xffffffffu, tm1, 2));
        float mn0 = fmaxf(m0, tm0), mn1 = fmaxf(m1, tm1);
        float cr0 = fexp2((m0 - mn0) * L2E);
        float cr1 = fexp2((m1 - mn1) * L2E);
        float rs0 = 0.f, rs1 = 0.f;
#pragma unroll
        for (int nt = 0; nt < 8; nt++) {
            sc[nt][0] = fexp2((sc[nt][0] - mn0) * L2E);
            sc[nt][1] = fexp2((sc[nt][1] - mn0) * L2E);
            sc[nt][2] = fexp2((sc[nt][2] - mn1) * L2E);
            sc[nt][3] = fexp2((sc[nt][3] - mn1) * L2E);
            rs0 += sc[nt][0] + sc[nt][1];
            rs1 += sc[nt][2] + sc[nt][3];
        }
        rs0 += __shfl_xor_sync(0xffffffffu, rs0, 1);
        rs0 += __shfl_xor_sync(0xffffffffu, rs0, 2);
        rs1 += __shfl_xor_sync(0xffffffffu, rs1, 1);
        rs1 += __shfl_xor_sync(0xffffffffu, rs1, 2);
        l0 = l0 * cr0 + rs0;
        l1 = l1 * cr1 + rs1;
        m0 = mn0; m1 = mn1;
#pragma unroll
        for (int nt = 0; nt < 8; nt++) {
            ao[nt][0] *= cr0; ao[nt][1] *= cr0;
            ao[nt][2] *= cr1; ao[nt][3] *= cr1;
        }

#pragma unroll
        for (int j = 0; j < 4; j++) {
            uint32_t pa[4];
#pragma unroll
            for (int u = 0; u < 2; u++) {
                __half2 H0 = __floats2half2_rn(sc[2 * j + u][0], sc[2 * j + u][1]);
                __half2 H1 = __floats2half2_rn(sc[2 * j + u][2], sc[2 * j + u][3]);
                pa[2 * u + 0] = *(uint32_t*)&H0;
                pa[2 * u + 1] = *(uint32_t*)&H1;
            }
#pragma unroll
            for (int gi = 0; gi < 4; gi++) {
                uint32_t v4[4];
                ldsm4(v4, sV + (gi * 16 + b_ro) * AT_PITCH + j * 32 + b_kb);
#pragma unroll
                for (int t = 0; t < 2; t++)
                    mma_f16(ao[gi * 2 + t], pa, &v4[t * 2]);
            }
        }
    }

    float i0 = 1.f / l0, i1 = 1.f / l1;
    int rowA = q0 + w * 16 + r0;
    int rowB = rowA + 8;
#pragma unroll
    for (int nt = 0; nt < 8; nt++) {
        int col = h * 64 + nt * 8 + cq * 2;
        size_t oA = ((size_t)(b * SEQ) + rowA) * 2048 + col;
        size_t oB = ((size_t)(b * SEQ) + rowB) * 2048 + col;
        *(__half2*)(OH + oA) = __floats2half2_rn(ao[nt][0] * i0, ao[nt][1] * i0);
        *(__half2*)(OH + oB) = __floats2half2_rn(ao[nt][2] * i1, ao[nt][3] * i1);
    }
}

// ---------------- host launch ----------------
extern "C" void kernel_launch(void* const* d_in, const int* in_sizes, int n_in,
                              void* d_out, int out_size)
{
    const float* hidden  = (const float*)d_in[0];
    const float* norm1_w = (const float*)d_in[2];
    const float* wq      = (const float*)d_in[3];
    const float* wk      = (const float*)d_in[4];
    const float* wv      = (const float*)d_in[5];
    const float* wo      = (const float*)d_in[6];
    const float* norm2_w = (const float*)d_in[7];
    const float* w_gate  = (const float*)d_in[8];
    const float* w_up    = (const float*)d_in[9];
    const float* w_down  = (const float*)d_in[10];
    float* out = (float*)d_out;

    float *res2;
    __half *qkvh, *ab, *wpool, *qb, *kbuf, *vtb, *mbuf;
    cudaGetSymbolAddress((void**)&res2, g_res2);
    cudaGetSymbolAddress((void**)&qkvh, g_qkvh);
    cudaGetSymbolAddress((void**)&mbuf, g_m);
    cudaGetSymbolAddress((void**)&ab,   g_a);
    cudaGetSymbolAddress((void**)&wpool, g_w);
    cudaGetSymbolAddress((void**)&qb,   g_q);
    cudaGetSymbolAddress((void**)&kbuf, g_k);
    cudaGetSymbolAddress((void**)&vtb,  g_vt);

    const size_t OQKV = 0;
    const size_t OWO  = 6ull * MEG;
    const size_t OGU  = 10ull * MEG;
    const size_t OWD  = 42ull * MEG;

    cudaFuncSetAttribute(hmma_gemm_kernel<1>, cudaFuncAttributeMaxDynamicSharedMemorySize, GSMEM);
    cudaFuncSetAttribute(hmma_gemm_kernel<3>, cudaFuncAttributeMaxDynamicSharedMemorySize, GSMEM);
    cudaFuncSetAttribute(hmma_gemm_kernel<4>, cudaFuncAttributeMaxDynamicSharedMemorySize, GSMEM);
    cudaFuncSetAttribute(attn_mma_kernel, cudaFuncAttributeMaxDynamicSharedMemorySize, AT_SMEM);

    // ---- weight conversions ----
    convT_kernel<<<dim3(32, 32), 256>>>(wq, wpool + OQKV, 2048, 2048);
    convT_kernel<<<dim3(8, 32), 256>>>(wk, wpool + OQKV + 2048ull * 2048, 2048, 512);
    convT_kernel<<<dim3(8, 32), 256>>>(wv, wpool + OQKV + 2560ull * 2048, 2048, 512);
    convT_kernel<<<dim3(32, 32), 256>>>(wo, wpool + OWO, 2048, 2048);
    convT_gu_kernel<<<dim3(128, 32), 256>>>(w_gate, w_up, wpool + OGU, 2048);
    convT_kernel<<<dim3(32, 128), 256>>>(w_down, wpool + OWD, 8192, 2048);

    // ---- 1. rmsnorm1 -> fp16 ----
    rmsnorm_h_kernel<<<ROWS, 256>>>(hidden, norm1_w, ab, HID);

    // ---- 2. fused QKV GEMM -> qkv fp16 ----
    hmma_gemm_kernel<3><<<dim3(3072 / 256, ROWS / 128), 256, GSMEM>>>(
        ab, wpool + OQKV, nullptr, nullptr, qkvh, 3072, 2048);

    // ---- 3. RoPE Q/K + V transpose ----
    rope_q_kernel<<<ROWS, NH * 32>>>(qkvh, qb);
    rope_k_kernel<<<ROWS, NKVH * 32>>>(qkvh, kbuf);
    vt_kernel<<<dim3(SEQ / 32, 2, NB * NKVH), dim3(32, 8)>>>(qkvh, vtb);

    // ---- 4. attention -> ctx fp16 (ab) ----
    attn_mma_kernel<<<dim3(NT, NH, NB), 128, AT_SMEM>>>(qb, kbuf, vtb, ab);

    // ---- 5. output projection + residual -> res2 fp32 ----
    hmma_gemm_kernel<1><<<dim3(2048 / 256, ROWS / 128), 256, GSMEM>>>(
        ab, wpool + OWO, hidden, res2, nullptr, 2048, 2048);

    // ---- 6. rmsnorm2 -> fp16 ----
    rmsnorm_h_kernel<<<ROWS, 256>>>(res2, norm2_w, ab, HID);

    // ---- 7. fused gate+up GEMM + silu-mul -> fp16 (mbuf) ----
    hmma_gemm_kernel<4><<<dim3(2 * FF / 256, ROWS / 128), 256, GSMEM>>>(
        ab, wpool + OGU, nullptr, nullptr, mbuf, FF, 2048);

    // ---- 8. down projection + residual -> out ----
    hmma_gemm_kernel<1><<<dim3(2048 / 256, ROWS / 128), 256, GSMEM>>>(
        mbuf, wpool + OWD, res2, out, nullptr, 2048, 8192);
}

// round 16
// speedup vs baseline: 1.5581x; 1.5341x over previous
#include <cuda_runtime.h>
#include <cuda_bf16.h>
#include <cuda_fp16.h>
#include <math.h>
#include <stdint.h>

// ---------------- problem constants ----------------
#define HID   2048
#define NH    32
#define NKVH  8
#define HD    64
#define FF    8192
#define SEQ   2048
#define NB    2
#define ROWS  4096
#define EPS   1e-6f
#define MEG   (1024*1024)
#define L2E   1.4426950408889634f
#define NT    (SEQ / 64)

// ---------------- scratch (device globals; no allocs allowed) ----------------
__device__ float  g_res2[(size_t)ROWS * 2048];
__device__ __half g_qkvh[(size_t)ROWS * 3072];
__device__ __half g_m  [(size_t)ROWS * FF];

__device__ __half g_a  [(size_t)ROWS * HID];
__device__ __half g_w  [(size_t)58 * MEG];

__device__ __half g_q  [(size_t)ROWS * 2048];
__device__ __half g_k  [(size_t)ROWS * 512];
__device__ __half g_vt [(size_t)ROWS * 512];

// ---------------- helpers ----------------
__device__ __forceinline__ uint32_t smem_u32(const void* p) {
    uint32_t a;
    asm("{ .reg .u64 t; cvta.to.shared.u64 t, %1; cvt.u32.u64 %0, t; }" : "=r"(a) : "l"(p));
    return a;
}

__device__ __forceinline__ void cpa16(uint32_t dst, const void* src) {
    asm volatile("cp.async.cg.shared.global [%0], [%1], 16;" :: "r"(dst), "l"(src));
}
__device__ __forceinline__ void cpa_commit() {
    asm volatile("cp.async.commit_group;" ::: "memory");
}

__device__ __forceinline__ void ldsm4(uint32_t* r, uint32_t addr) {
    asm volatile("ldmatrix.sync.aligned.m8n8.x4.shared.b16 {%0,%1,%2,%3}, [%4];"
        : "=r"(r[0]), "=r"(r[1]), "=r"(r[2]), "=r"(r[3]) : "r"(addr));
}

__device__ __forceinline__ void mma_f16(float* c, const uint32_t* a, const uint32_t* b) {
    asm volatile("mma.sync.aligned.m16n8k16.row.col.f32.f16.f16.f32 "
        "{%0,%1,%2,%3}, {%4,%5,%6,%7}, {%8,%9}, {%0,%1,%2,%3};"
        : "+f"(c[0]), "+f"(c[1]), "+f"(c[2]), "+f"(c[3])
        : "r"(a[0]), "r"(a[1]), "r"(a[2]), "r"(a[3]), "r"(b[0]), "r"(b[1]));
}

__device__ __forceinline__ float fexp2(float z) {
    z = fminf(fmaxf(z, -126.f), 126.f);
    float sh = z + 12582912.f;
    float zi = sh - 12582912.f;
    float f = z - zi;
    float p = 0.0013333558f;
    p = p * f + 0.0096181291f;
    p = p * f + 0.0555041087f;
    p = p * f + 0.2402265070f;
    p = p * f + 0.6931471806f;
    p = p * f + 1.0f;
    int ei = __float_as_int(sh) - 0x4B400000;
    return p * __int_as_float((ei + 127) << 23);
}

__device__ __forceinline__ float fsilu(float x) {
    return x / (1.f + fexp2(-x * L2E));
}

// ---------------- converters ----------------
__global__ void convT_kernel(const float* __restrict__ W,
                             __half* __restrict__ wT, int K, int N)
{
    __shared__ float t[64][67];
    int n0 = blockIdx.x * 64, k0 = blockIdx.y * 64;
    int tx = threadIdx.x & 31, ty = threadIdx.x >> 5;
    int cx = threadIdx.x & 15;
    int ry = threadIdx.x >> 4;
    for (int ky = ry; ky < 64; ky += 16) {
        float4 v = *(const float4*)(W + (size_t)(k0 + ky) * N + n0 + cx * 4);
        t[ky][cx * 4 + 0] = v.x; t[ky][cx * 4 + 1] = v.y;
        t[ky][cx * 4 + 2] = v.z; t[ky][cx * 4 + 3] = v.w;
    }
    __syncthreads();
    for (int ny = ty; ny < 64; ny += 8) {
        __half2 h;
        h.x = __float2half_rn(t[2 * tx][ny]);
        h.y = __float2half_rn(t[2 * tx + 1][ny]);
        *(__half2*)(wT + (size_t)(n0 + ny) * K + k0 + 2 * tx) = h;
    }
}

__global__ void convT_gu_kernel(const float* __restrict__ G,
                                const float* __restrict__ U,
                                __half* __restrict__ wT, int K)
{
    __shared__ float tg[64][67];
    __shared__ float tu[64][67];
    int n0 = blockIdx.x * 64, k0 = blockIdx.y * 64;
    int tx = threadIdx.x & 31, ty = threadIdx.x >> 5;
    int cx = threadIdx.x & 15;
    int ry = threadIdx.x >> 4;
    for (int ky = ry; ky < 64; ky += 16) {
        float4 v = *(const float4*)(G + (size_t)(k0 + ky) * FF + n0 + cx * 4);
        tg[ky][cx * 4 + 0] = v.x; tg[ky][cx * 4 + 1] = v.y;
        tg[ky][cx * 4 + 2] = v.z; tg[ky][cx * 4 + 3] = v.w;
        float4 u = *(const float4*)(U + (size_t)(k0 + ky) * FF + n0 + cx * 4);
        tu[ky][cx * 4 + 0] = u.x; tu[ky][cx * 4 + 1] = u.y;
        tu[ky][cx * 4 + 2] = u.z; tu[ky][cx * 4 + 3] = u.w;
    }
    __syncthreads();
    for (int ny = ty; ny < 64; ny += 8) {
        int n = n0 + ny;
        size_t rowG = (size_t)((n >> 7) * 256 + ((n >> 6) & 1) * 128 + ((n >> 3) & 7) * 16 + (n & 7));
        __half2 h;
        h.x = __float2half_rn(tg[2 * tx][ny]);
        h.y = __float2half_rn(tg[2 * tx + 1][ny]);
        *(__half2*)(wT + rowG * K + k0 + 2 * tx) = h;
        h.x = __float2half_rn(tu[2 * tx][ny]);
        h.y = __float2half_rn(tu[2 * tx + 1][ny]);
        *(__half2*)(wT + (rowG + 8) * K + k0 + 2 * tx) = h;
    }
}

// RMSNorm -> fp16
__global__ void rmsnorm_h_kernel(const float* __restrict__ x,
                                 const float* __restrict__ w,
                                 __half* __restrict__ o, int K)
{
    int row = blockIdx.x;
    const float* xr = x + (size_t)row * K;
    float ss = 0.f;
    int nvec = K / 4;
    const float4* xv = (const float4*)xr;
    for (int c = threadIdx.x; c < nvec; c += blockDim.x) {
        float4 v = xv[c];
        ss += v.x * v.x + v.y * v.y + v.z * v.z + v.w * v.w;
    }
    __shared__ float red[32];
    for (int off = 16; off > 0; off >>= 1) ss += __shfl_xor_sync(0xffffffffu, ss, off);
    int lane = threadIdx.x & 31, wid = threadIdx.x >> 5;
    if (lane == 0) red[wid] = ss;
    __syncthreads();
    int nwarp = blockDim.x >> 5;
    if (wid == 0) {
        float t = (lane < nwarp) ? red[lane] : 0.f;
        for (int off = 16; off > 0; off >>= 1) t += __shfl_xor_sync(0xffffffffu, t, off);
        if (lane == 0) red[0] = t;
    }
    __syncthreads();
    float inv = rsqrtf(red[0] / (float)K + EPS);

    for (int c = threadIdx.x; c < K / 2; c += blockDim.x) {
        int k = 2 * c;
        __half2 h;
        h.x = __float2half_rn(xr[k] * inv * w[k]);
        h.y = __float2half_rn(xr[k + 1] * inv * w[k + 1]);
        ((__half2*)(o + (size_t)row * K))[c] = h;
    }
}

// RoPE Q (reads fp16 qkv)
__global__ void rope_q_kernel(const __half* __restrict__ x, __half* __restrict__ o)
{
    int row = blockIdx.x;
    int b = row >> 11, s = row & 2047;
    int t = threadIdx.x;
    int h = t >> 5, i = t & 31;
    float inv_freq = powf(10000.0f, -(float)(2 * i) / 64.0f);
    float ang = (float)s * inv_freq;
    float c, sn;
    __sincosf(ang, &sn, &c);
    const __half* p = x + (size_t)row * 3072 + h * HD;
    float x1 = __half2float(p[i]), x2 = __half2float(p[i + 32]);
    size_t dst = ((size_t)(b * NH + h) * SEQ + s) * 64;
    o[dst + i]      = __float2half_rn((x1 * c - x2 * sn) * 0.125f);
    o[dst + i + 32] = __float2half_rn((x2 * c + x1 * sn) * 0.125f);
}

// RoPE K (reads fp16 qkv)
__global__ void rope_k_kernel(const __half* __restrict__ x, __half* __restrict__ o)
{
    int row = blockIdx.x;
    int b = row >> 11, s = row & 2047;
    int t = threadIdx.x;
    int h = t >> 5, i = t & 31;
    float inv_freq = powf(10000.0f, -(float)(2 * i) / 64.0f);
    float ang = (float)s * inv_freq;
    float c, sn;
    __sincosf(ang, &sn, &c);
    const __half* p = x + (size_t)row * 3072 + 2048 + h * HD;
    float x1 = __half2float(p[i]), x2 = __half2float(p[i + 32]);
    size_t dst = ((size_t)(b * NKVH + h) * SEQ + s) * 64;
    o[dst + i]      = __float2half_rn(x1 * c - x2 * sn);
    o[dst + i + 32] = __float2half_rn(x2 * c + x1 * sn);
}

// V transpose (reads fp16 qkv)
__global__ void vt_kernel(const __half* __restrict__ v, __half* __restrict__ oT)
{
    __shared__ __half t[32][34];
    int s0 = blockIdx.x * 32, d0 = blockIdx.y * 32;
    int bz = blockIdx.z;
    int b = bz >> 3, kvh = bz & 7;
    int tx = threadIdx.x, ty = threadIdx.y;
    for (int sy = ty; sy < 32; sy += 8)
        t[sy][tx] = v[(size_t)(b * SEQ + s0 + sy) * 3072 + 2560 + kvh * 64 + d0 + tx];
    __syncthreads();
    for (int dy = ty; dy < 32; dy += 8)
        oT[((size_t)bz * 64 + d0 + dy) * SEQ + s0 + tx] = t[tx][dy];
}

// ---------------- HMMA GEMM: 128x256 tile, BK=32, 4-stage (R13 verified) ----------------
#define APITCH 80
#define A_MAT  10240
#define B_MAT  20480
#define STG_SZ (A_MAT + B_MAT)
#define GSMEM  (4 * STG_SZ)

template<int EPI>
__global__ void __launch_bounds__(256, 1)
hmma_gemm_kernel(const __half* __restrict__ A, const __half* __restrict__ B,
                 const float* __restrict__ RES,
                 float* __restrict__ C, __half* __restrict__ OH, int N, int K)
{
    extern __shared__ char sm[];
    uint32_t smb = smem_u32(sm);
    int tid = threadIdx.x, lane = tid & 31, wid = tid >> 5;
    int wm = wid & 3, wn = wid >> 2;
    int bm = blockIdx.y, bn = blockIdx.x;
    int NKT = K / 32;

    const __half* gA = A + (size_t)bm * 128 * K;
    const __half* gB = B + (size_t)bn * 256 * K;

    int rbase = tid >> 2;
    int ch = tid & 3;

    auto issue = [&](int st, int kt) {
        uint32_t base = smb + st * STG_SZ;
        int koff = kt * 32 + ch * 8;
#pragma unroll
        for (int u = 0; u < 2; u++) {
            int r = rbase + u * 64;
            cpa16(base + r * APITCH + ch * 16, gA + (size_t)r * K + koff);
        }
        uint32_t bB = base + A_MAT;
#pragma unroll
        for (int u = 0; u < 4; u++) {
            int r = rbase + u * 64;
            cpa16(bB + r * APITCH + ch * 16, gB + (size_t)r * K + koff);
        }
        cpa_commit();
    };

    float acc[2][16][4];
#pragma unroll
    for (int s = 0; s < 2; s++)
#pragma unroll
        for (int t = 0; t < 16; t++)
#pragma unroll
            for (int j = 0; j < 4; j++) acc[s][t][j] = 0.f;

    issue(0, 0);
    issue(1, 1);
    issue(2, 2);

    int a_row = wm * 32 + (lane & 15);
    int a_kb  = (lane >> 4) * 16;
    int b_ro  = ((lane >> 4) << 3) + (lane & 7);
    int b_kb  = ((lane >> 3) & 1) * 16;

    for (int kt = 0; kt < NKT; kt++) {
        int st = kt & 3;
        asm volatile("cp.async.wait_group 2;" ::: "memory");
        __syncthreads();
        if (kt + 3 < NKT) issue((kt + 3) & 3, kt + 3);
        else cpa_commit();

        uint32_t sA = smb + st * STG_SZ;
        uint32_t sB = sA + A_MAT;

#pragma unroll
        for (int ks = 0; ks < 2; ks++) {
            int kB = ks * 32;
            uint32_t a4[2][4];
            ldsm4(a4[0], sA + (a_row)      * APITCH + kB + a_kb);
            ldsm4(a4[1], sA + (a_row + 16) * APITCH + kB + a_kb);
#pragma unroll
            for (int gi = 0; gi < 8; gi++) {
                int brow = wn * 128 + gi * 16 + b_ro;
                uint32_t b4[4];
                ldsm4(b4, sB + brow * APITCH + kB + b_kb);
#pragma unroll
                for (int t = 0; t < 2; t++) {
                    const uint32_t* bp = &b4[t * 2];
#pragma unroll
                    for (int sub = 0; sub < 2; sub++)
                        mma_f16(acc[sub][gi * 2 + t], a4[sub], bp);
                }
            }
        }
    }

    // epilogue
#pragma unroll
    for (int sub = 0; sub < 2; sub++) {
        int row0 = bm * 128 + wm * 32 + sub * 16 + (lane >> 2);
        if (EPI == 4) {
#pragma unroll
            for (int j = 0; j < 8; j++) {
                int col = bn * 128 + wn * 64 + j * 8 + (lane & 3) * 2;
                size_t o0 = (size_t)row0 * FF + col;
                size_t o1 = o0 + (size_t)8 * FF;
                float* g = acc[sub][2 * j];
                float* u = acc[sub][2 * j + 1];
                __half2 H0, H1;
                H0.x = __float2half_rn(fsilu(g[0]) * u[0]);
                H0.y = __float2half_rn(fsilu(g[1]) * u[1]);
                H1.x = __float2half_rn(fsilu(g[2]) * u[2]);
                H1.y = __float2half_rn(fsilu(g[3]) * u[3]);
                *(__half2*)(OH + o0) = H0;
                *(__half2*)(OH + o1) = H1;
            }
        } else {
#pragma unroll
            for (int t = 0; t < 16; t++) {
                int col = bn * 256 + wn * 128 + t * 8 + (lane & 3) * 2;
                size_t o0 = (size_t)row0 * N + col;
                size_t o1 = o0 + (size_t)8 * N;
                if (EPI == 3) {
                    __half2 H0, H1;
                    H0.x = __float2half_rn(acc[sub][t][0]);
                    H0.y = __float2half_rn(acc[sub][t][1]);
                    H1.x = __float2half_rn(acc[sub][t][2]);
                    H1.y = __float2half_rn(acc[sub][t][3]);
                    *(__half2*)(OH + o0) = H0;
                    *(__half2*)(OH + o1) = H1;
                } else {
                    float2 v0 = make_float2(acc[sub][t][0], acc[sub][t][1]);
                    float2 v1 = make_float2(acc[sub][t][2], acc[sub][t][3]);
                    if (EPI == 1) {
                        float2 r0 = *(const float2*)(RES + o0);
                        float2 r1 = *(const float2*)(RES + o1);
                        v0.x += r0.x; v0.y += r0.y;
                        v1.x += r1.x; v1.y += r1.y;
                    }
                    *(float2*)(C + o0) = v0;
                    *(float2*)(C + o1) = v1;
                }
            }
        }
    }
}

// ---------------- tensor-core causal attention (R13 + early KV prefetch) ----------------
#define AT_PITCH 144
#define AT_MAT   (64 * AT_PITCH)
#define AT_Q   0
#define AT_KV  (AT_MAT)
#define AT_SMEM (AT_MAT + 2 * 2 * AT_MAT)   // 46080

__global__ void __launch_bounds__(128)
attn_mma_kernel(const __half* __restrict__ qq, const __half* __restrict__ kk,
                const __half* __restrict__ vt, __half* __restrict__ OH)
{
    extern __shared__ char sm[];
    uint32_t smb = smem_u32(sm);
    int qt = blockIdx.x, h = blockIdx.y, b = blockIdx.z;
    int kvh = h >> 2;
    int tid = threadIdx.x, lane = tid & 31, w = tid >> 5;
    int q0 = qt * 64;

    const __half* Qp = qq + ((size_t)(b * NH + h) * SEQ + q0) * 64;
    const __half* Kp = kk + ((size_t)(b * NKVH + kvh) * SEQ) * 64;
    const __half* Vp = vt + ((size_t)(b * NKVH + kvh) * 64) * SEQ;

    auto issue_kv = [&](int st, int kt) {
        int k0 = kt * 64;
        uint32_t base = smb + AT_KV + st * (2 * AT_MAT);
#pragma unroll
        for (int it = 0; it < 4; it++) {
            int idx = it * 128 + tid;
            int r = idx >> 3, ch = idx & 7;
            cpa16(base + r * AT_PITCH + ch * 16,          Kp + (size_t)(k0 + r) * 64 + ch * 8);
            cpa16(base + AT_MAT + r * AT_PITCH + ch * 16, Vp + (size_t)r * SEQ + k0 + ch * 8);
        }
        cpa_commit();
    };

    // issue Q load AND first K/V prefetch before waiting on either
#pragma unroll
    for (int it = 0; it < 4; it++) {
        int idx = it * 128 + tid;
        int r = idx >> 3, ch = idx & 7;
        cpa16(smb + AT_Q + r * AT_PITCH + ch * 16, Qp + (size_t)r * 64 + ch * 8);
    }
    cpa_commit();
    issue_kv(0, 0);
    asm volatile("cp.async.wait_group 0;" ::: "memory");
    __syncthreads();

    int r0 = lane >> 2, cq = lane & 3;
    int a_row = w * 16 + (lane & 15);
    int a_kb  = (lane >> 4) * 16;
    int b_ro  = ((lane >> 4) << 3) + (lane & 7);
    int b_kb  = ((lane >> 3) & 1) * 16;

    uint32_t qf[4][4];
#pragma unroll
    for (int kc = 0; kc < 4; kc++)
        ldsm4(qf[kc], smb + AT_Q + a_row * AT_PITCH + kc * 32 + a_kb);

    float m0 = -1e30f, m1 = -1e30f, l0 = 0.f, l1 = 0.f;
    float ao[8][4];
#pragma unroll
    for (int nt = 0; nt < 8; nt++)
#pragma unroll
        for (int j = 0; j < 4; j++) ao[nt][j] = 0.f;

    for (int kt = 0; kt <= qt; kt++) {
        int st = kt & 1;
        asm volatile("cp.async.wait_group 0;" ::: "memory");
        __syncthreads();
        if (kt < qt) issue_kv((kt + 1) & 1, kt + 1);

        uint32_t sK = smb + AT_KV + st * (2 * AT_MAT);
        uint32_t sV = sK + AT_MAT;

        float sc[8][4];
#pragma unroll
        for (int nt = 0; nt < 8; nt++)
#pragma unroll
            for (int j = 0; j < 4; j++) sc[nt][j] = 0.f;

#pragma unroll
        for (int kc = 0; kc < 4; kc++) {
#pragma unroll
            for (int gi = 0; gi < 4; gi++) {
                uint32_t k4[4];
                ldsm4(k4, sK + (gi * 16 + b_ro) * AT_PITCH + kc * 32 + b_kb);
#pragma unroll
                for (int t = 0; t < 2; t++)
                    mma_f16(sc[gi * 2 + t], qf[kc], &k4[t * 2]);
            }
        }

        if (kt == qt) {
            int qr0 = w * 16 + r0, qr1 = qr0 + 8;
#pragma unroll
            for (int nt = 0; nt < 8; nt++) {
                int col = nt * 8 + cq * 2;
                if (col     > qr0) sc[nt][0] = -1e30f;
                if (col + 1 > qr0) sc[nt][1] = -1e30f;
                if (col     > qr1) sc[nt][2] = -1e30f;
                if (col + 1 > qr1) sc[nt][3] = -1e30f;
            }
        }

        float tm0 = -1e30f, tm1 = -1e30f;
#pragma unroll
        for (int nt = 0; nt < 8; nt++) {
            tm0 = fmaxf(tm0, fmaxf(sc[nt][0], sc[nt][1]));
            tm1 = fmaxf(tm1, fmaxf(sc[nt][2], sc[nt][3]));
        }
        tm0 = fmaxf(tm0, __shfl_xor_sync(0xffffffffu, tm0, 1));
        tm0 = fmaxf(tm0, __shfl_xor_sync(0xffffffffu, tm0, 2));
        tm1 = fmaxf(tm1, __shfl_xor_sync(0xffffffffu, tm1, 1));
        tm1 = fmaxf(tm1, __shfl_xor_sync(0xffffffffu, tm1, 2));
        float mn0 = fmaxf(m0, tm0), mn1 = fmaxf(m1, tm1);
        float cr0 = fexp2((m0 - mn0) * L2E);
        float cr1 = fexp2((m1 - mn1) * L2E);
        float rs0 = 0.f, rs1 = 0.f;
#pragma unroll
        for (int nt = 0; nt < 8; nt++) {
            sc[nt][0] = fexp2((sc[nt][0] - mn0) * L2E);
            sc[nt][1] = fexp2((sc[nt][1] - mn0) * L2E);
            sc[nt][2] = fexp2((sc[nt][2] - mn1) * L2E);
            sc[nt][3] = fexp2((sc[nt][3] - mn1) * L2E);
            rs0 += sc[nt][0] + sc[nt][1];
            rs1 += sc[nt][2] + sc[nt][3];
        }
        rs0 += __shfl_xor_sync(0xffffffffu, rs0, 1);
        rs0 += __shfl_xor_sync(0xffffffffu, rs0, 2);
        rs1 += __shfl_xor_sync(0xffffffffu, rs1, 1);
        rs1 += __shfl_xor_sync(0xffffffffu, rs1, 2);
        l0 = l0 * cr0 + rs0;
        l1 = l1 * cr1 + rs1;
        m0 = mn0; m1 = mn1;
#pragma unroll
        for (int nt = 0; nt < 8; nt++) {
            ao[nt][0] *= cr0; ao[nt][1] *= cr0;
            ao[nt][2] *= cr1; ao[nt][3] *= cr1;
        }

#pragma unroll
        for (int j = 0; j < 4; j++) {
            uint32_t pa[4];
#pragma unroll
            for (int u = 0; u < 2; u++) {
                __half2 H0 = __floats2half2_rn(sc[2 * j + u][0], sc[2 * j + u][1]);
                __half2 H1 = __floats2half2_rn(sc[2 * j + u][2], sc[2 * j + u][3]);
                pa[2 * u + 0] = *(uint32_t*)&H0;
                pa[2 * u + 1] = *(uint32_t*)&H1;
            }
#pragma unroll
            for (int gi = 0; gi < 4; gi++) {
                uint32_t v4[4];
                ldsm4(v4, sV + (gi * 16 + b_ro) * AT_PITCH + j * 32 + b_kb);
#pragma unroll
                for (int t = 0; t < 2; t++)
                    mma_f16(ao[gi * 2 + t], pa, &v4[t * 2]);
            }
        }
    }

    float i0 = 1.f / l0, i1 = 1.f / l1;
    int rowA = q0 + w * 16 + r0;
    int rowB = rowA + 8;
#pragma unroll
    for (int nt = 0; nt < 8; nt++) {
        int col = h * 64 + nt * 8 + cq * 2;
        size_t oA = ((size_t)(b * SEQ) + rowA) * 2048 + col;
        size_t oB = ((size_t)(b * SEQ) + rowB) * 2048 + col;
        *(__half2*)(OH + oA) = __floats2half2_rn(ao[nt][0] * i0, ao[nt][1] * i0);
        *(__half2*)(OH + oB) = __floats2half2_rn(ao[nt][2] * i1, ao[nt][3] * i1);
    }
}

// ---------------- host launch ----------------
extern "C" void kernel_launch(void* const* d_in, const int* in_sizes, int n_in,
                              void* d_out, int out_size)
{
    const float* hidden  = (const float*)d_in[0];
    const float* norm1_w = (const float*)d_in[2];
    const float* wq      = (const float*)d_in[3];
    const float* wk      = (const float*)d_in[4];
    const float* wv      = (const float*)d_in[5];
    const float* wo      = (const float*)d_in[6];
    const float* norm2_w = (const float*)d_in[7];
    const float* w_gate  = (const float*)d_in[8];
    const float* w_up    = (const float*)d_in[9];
    const float* w_down  = (const float*)d_in[10];
    float* out = (float*)d_out;

    float *res2;
    __half *qkvh, *ab, *wpool, *qb, *kbuf, *vtb, *mbuf;
    cudaGetSymbolAddress((void**)&res2, g_res2);
    cudaGetSymbolAddress((void**)&qkvh, g_qkvh);
    cudaGetSymbolAddress((void**)&mbuf, g_m);
    cudaGetSymbolAddress((void**)&ab,   g_a);
    cudaGetSymbolAddress((void**)&wpool, g_w);
    cudaGetSymbolAddress((void**)&qb,   g_q);
    cudaGetSymbolAddress((void**)&kbuf, g_k);
    cudaGetSymbolAddress((void**)&vtb,  g_vt);

    const size_t OQKV = 0;
    const size_t OWO  = 6ull * MEG;
    const size_t OGU  = 10ull * MEG;
    const size_t OWD  = 42ull * MEG;

    cudaFuncSetAttribute(hmma_gemm_kernel<1>, cudaFuncAttributeMaxDynamicSharedMemorySize, GSMEM);
    cudaFuncSetAttribute(hmma_gemm_kernel<3>, cudaFuncAttributeMaxDynamicSharedMemorySize, GSMEM);
    cudaFuncSetAttribute(hmma_gemm_kernel<4>, cudaFuncAttributeMaxDynamicSharedMemorySize, GSMEM);
    cudaFuncSetAttribute(attn_mma_kernel, cudaFuncAttributeMaxDynamicSharedMemorySize, AT_SMEM);

    // ---- weight conversions ----
    convT_kernel<<<dim3(32, 32), 256>>>(wq, wpool + OQKV, 2048, 2048);
    convT_kernel<<<dim3(8, 32), 256>>>(wk, wpool + OQKV + 2048ull * 2048, 2048, 512);
    convT_kernel<<<dim3(8, 32), 256>>>(wv, wpool + OQKV + 2560ull * 2048, 2048, 512);
    convT_kernel<<<dim3(32, 32), 256>>>(wo, wpool + OWO, 2048, 2048);
    convT_gu_kernel<<<dim3(128, 32), 256>>>(w_gate, w_up, wpool + OGU, 2048);
    convT_kernel<<<dim3(32, 128), 256>>>(w_down, wpool + OWD, 8192, 2048);

    // ---- 1. rmsnorm1 -> fp16 ----
    rmsnorm_h_kernel<<<ROWS, 256>>>(hidden, norm1_w, ab, HID);

    // ---- 2. fused QKV GEMM -> qkv fp16 ----
    hmma_gemm_kernel<3><<<dim3(3072 / 256, ROWS / 128), 256, GSMEM>>>(
        ab, wpool + OQKV, nullptr, nullptr, qkvh, 3072, 2048);

    // ---- 3. RoPE Q/K + V transpose ----
    rope_q_kernel<<<ROWS, NH * 32>>>(qkvh, qb);
    rope_k_kernel<<<ROWS, NKVH * 32>>>(qkvh, kbuf);
    vt_kernel<<<dim3(SEQ / 32, 2, NB * NKVH), dim3(32, 8)>>>(qkvh, vtb);

    // ---- 4. attention -> ctx fp16 (ab) ----
    attn_mma_kernel<<<dim3(NT, NH, NB), 128, AT_SMEM>>>(qb, kbuf, vtb, ab);

    // ---- 5. output projection + residual -> res2 fp32 ----
    hmma_gemm_kernel<1><<<dim3(2048 / 256, ROWS / 128), 256, GSMEM>>>(
        ab, wpool + OWO, hidden, res2, nullptr, 2048, 2048);

    // ---- 6. rmsnorm2 -> fp16 ----
    rmsnorm_h_kernel<<<ROWS, 256>>>(res2, norm2_w, ab, HID);

    // ---- 7. fused gate+up GEMM + silu-mul -> fp16 (mbuf) ----
    hmma_gemm_kernel<4><<<dim3(2 * FF / 256, ROWS / 128), 256, GSMEM>>>(
        ab, wpool + OGU, nullptr, nullptr, mbuf, FF, 2048);

    // ---- 8. down projection + residual -> out ----
    hmma_gemm_kernel<1><<<dim3(2048 / 256, ROWS / 128), 256, GSMEM>>>(
        mbuf, wpool + OWD, res2, out, nullptr, 2048, 8192);
}